// round 5
// baseline (speedup 1.0000x reference)
#include <cuda_runtime.h>
#include <cstdint>

#define NN 8192
#define DD 128
#define NC 10
#define BM 128
#define BN 128
#define JSPLIT 2
#define JCHUNK (NN / JSPLIT)
#define TILES (JCHUNK / BN)
#define NT 512

// ---- device globals ----
__device__ float    g_x2[NN];
__device__ float    g_S[NN][NC];
__device__ unsigned g_mp[NN];
__device__ int      g_order[NN];
__device__ int      g_scls[NN];
__device__ float    g_sx2[NN];
__device__ int      g_cstart[NC];
__device__ int      g_count[NC];

#define FFMA2(acc, a, b) \
    asm("fma.rn.f32x2 %0, %1, %2, %0;" : "+l"(acc) : "l"(a), "l"(b))
#define PACK2(dst, f) \
    asm("mov.b64 %0, {%1, %1};" : "=l"(dst) : "r"(__float_as_uint(f)))

// ---------------------------------------------------------------------------
// Kernel 1: row norms + zero g_S, g_mp, out
// ---------------------------------------------------------------------------
__global__ void bh_prep(const float* __restrict__ E, float* __restrict__ out)
{
    int r = blockIdx.x * blockDim.x + threadIdx.x;
    if (r == 0) out[0] = 0.0f;
    if (r < NN) {
        const float4* p = reinterpret_cast<const float4*>(E + (size_t)r * DD);
        float s = 0.f;
#pragma unroll
        for (int k = 0; k < DD / 4; k++) {
            float4 v = p[k];
            s += v.x * v.x + v.y * v.y + v.z * v.z + v.w * v.w;
        }
        g_x2[r] = s;
        g_mp[r] = 0u;
#pragma unroll
        for (int c = 0; c < NC; c++) g_S[r][c] = 0.f;
    }
}

// ---------------------------------------------------------------------------
// Kernel 2: counts, class starts, stable (class,index) sort -> order/cls/x2
// ---------------------------------------------------------------------------
__global__ void bh_table(const int* __restrict__ labels)
{
    __shared__ int sl[NN];
    __shared__ int cnt[NC][256];
    __shared__ int tot[NC], cst[NC];

    const int tid = threadIdx.x;
    for (int i = tid; i < NN; i += 256) sl[i] = labels[i];
    __syncthreads();

    const int base = tid * 32;
    int lc[NC];
#pragma unroll
    for (int c = 0; c < NC; c++) lc[c] = 0;
    for (int i = 0; i < 32; i++) {
        int lbl = sl[base + i];
#pragma unroll
        for (int c = 0; c < NC; c++) lc[c] += (lbl == c);
    }
#pragma unroll
    for (int c = 0; c < NC; c++) cnt[c][tid] = lc[c];
    __syncthreads();

    if (tid < NC) {
        int run = 0;
        for (int t = 0; t < 256; t++) { int tmp = cnt[tid][t]; cnt[tid][t] = run; run += tmp; }
        tot[tid] = run;
        g_count[tid] = run;
    }
    __syncthreads();
    if (tid == 0) {
        int run = 0;
        for (int c = 0; c < NC; c++) { cst[c] = run; g_cstart[c] = run; run += tot[c]; }
    }
    __syncthreads();

#pragma unroll
    for (int c = 0; c < NC; c++) lc[c] = 0;
    for (int i = 0; i < 32; i++) {
        int gi = base + i;
        int c  = sl[gi];
        int pos = cst[c] + cnt[c][tid] + lc[c]++;
        g_order[pos] = gi;
        g_scls[pos]  = c;
        g_sx2[pos]   = g_x2[gi];
    }
}

// ---------------------------------------------------------------------------
// Kernel 3: main — 128x128 tile, 512 threads (4 warps/SMSP), 4x8 micro-tile,
// f32x2 FMAs packed along j, double-buffered B, sorted-column epilogue.
// ---------------------------------------------------------------------------
__global__ __launch_bounds__(NT, 1)
void bh_main(const float* __restrict__ E, const int* __restrict__ labels)
{
    extern __shared__ float sm[];
    float* As  = sm;                    // [DD][BM]
    float* Bs  = As + DD * BM;          // [2][DD][BN]
    float* sxj = Bs + 2 * DD * BN;      // [2][BN]
    int*   scl = (int*)(sxj + 2 * BN);  // [2][BN]
    float* sS  = (float*)(scl + 2 * BN);// [BM][NC]

    const int tid  = threadIdx.x;
    const int tx   = tid & 15;          // 16 col groups x 8 cols
    const int ty   = tid >> 4;          // 32 row groups x 4 rows
    const int row0 = blockIdx.x * BM;
    const int j0   = blockIdx.y * JCHUNK;

    for (int i = tid; i < BM * NC; i += NT) sS[i] = 0.f;

    // ---- A tile: k-major ----
#pragma unroll
    for (int it = 0; it < 8; ++it) {
        int idx = tid + it * NT;
        int r   = idx & (BM - 1);
        int k4  = idx >> 7;
        float4 v = *reinterpret_cast<const float4*>(E + (size_t)(row0 + r) * DD + k4 * 4);
        As[(k4 * 4 + 0) * BM + r] = v.x;
        As[(k4 * 4 + 1) * BM + r] = v.y;
        As[(k4 * 4 + 2) * BM + r] = v.z;
        As[(k4 * 4 + 3) * BM + r] = v.w;
    }
    // ---- B tile 0 (gathered via sorted order) ----
#pragma unroll
    for (int it = 0; it < 8; ++it) {
        int idx = tid + it * NT;
        int r   = idx & (BN - 1);
        int k4  = idx >> 7;
        int orig = g_order[j0 + r];
        float4 v = *reinterpret_cast<const float4*>(E + (size_t)orig * DD + k4 * 4);
        Bs[(k4 * 4 + 0) * BN + r] = v.x;
        Bs[(k4 * 4 + 1) * BN + r] = v.y;
        Bs[(k4 * 4 + 2) * BN + r] = v.z;
        Bs[(k4 * 4 + 3) * BN + r] = v.w;
    }
    if (tid < BN) { sxj[tid] = g_sx2[j0 + tid]; scl[tid] = g_scls[j0 + tid]; }

    float ax[4], accr[4], mpv[4];
    int   myl[4];
#pragma unroll
    for (int i = 0; i < 4; ++i) {
        ax[i]   = g_x2[row0 + ty * 4 + i];
        myl[i]  = labels[row0 + ty * 4 + i];
        accr[i] = 0.f;
        mpv[i]  = 0.f;
    }
    int prevc = g_scls[j0 + tx * 2];

    for (int t = 0; t < TILES; ++t) {
        __syncthreads();
        const int cur = t & 1, nxt = cur ^ 1;
        const int jb  = j0 + (t + 1) * BN;
        const bool more = (t + 1 < TILES);
        float* Bcur = Bs + cur * DD * BN;
        float* Bnxt = Bs + nxt * DD * BN;

        unsigned long long acc[4][4];
#pragma unroll
        for (int i = 0; i < 4; ++i)
#pragma unroll
            for (int m = 0; m < 4; ++m) acc[i][m] = 0ull;

        float4 st[4];
        if (more) {
#pragma unroll
            for (int s = 0; s < 4; ++s) {
                int idx = tid + s * NT;
                int r = idx & (BN - 1), k4 = idx >> 7;
                st[s] = *reinterpret_cast<const float4*>(
                    E + (size_t)g_order[jb + r] * DD + k4 * 4);
            }
        }

#pragma unroll 4
        for (int k = 0; k < DD / 2; ++k) {
            float4 a0 = *reinterpret_cast<const float4*>(&As[k * BM + ty * 4]);
            unsigned long long bb[4];
#pragma unroll
            for (int m = 0; m < 4; ++m)
                bb[m] = *reinterpret_cast<const unsigned long long*>(
                    &Bcur[k * BN + tx * 2 + 32 * m]);
            unsigned long long av[4];
            PACK2(av[0], a0.x); PACK2(av[1], a0.y); PACK2(av[2], a0.z); PACK2(av[3], a0.w);
#pragma unroll
            for (int i = 0; i < 4; ++i)
#pragma unroll
                for (int m = 0; m < 4; ++m)
                    FFMA2(acc[i][m], av[i], bb[m]);
        }

        if (more) {
#pragma unroll
            for (int s = 0; s < 4; ++s) {
                int idx = tid + s * NT;
                int r = idx & (BN - 1), k4 = idx >> 7;
                Bnxt[(k4 * 4 + 0) * BN + r] = st[s].x;
                Bnxt[(k4 * 4 + 1) * BN + r] = st[s].y;
                Bnxt[(k4 * 4 + 2) * BN + r] = st[s].z;
                Bnxt[(k4 * 4 + 3) * BN + r] = st[s].w;
            }
#pragma unroll
            for (int s = 4; s < 8; ++s) {
                int idx = tid + s * NT;
                int r = idx & (BN - 1), k4 = idx >> 7;
                st[s - 4] = *reinterpret_cast<const float4*>(
                    E + (size_t)g_order[jb + r] * DD + k4 * 4);
            }
        }

#pragma unroll 4
        for (int k = DD / 2; k < DD; ++k) {
            float4 a0 = *reinterpret_cast<const float4*>(&As[k * BM + ty * 4]);
            unsigned long long bb[4];
#pragma unroll
            for (int m = 0; m < 4; ++m)
                bb[m] = *reinterpret_cast<const unsigned long long*>(
                    &Bcur[k * BN + tx * 2 + 32 * m]);
            unsigned long long av[4];
            PACK2(av[0], a0.x); PACK2(av[1], a0.y); PACK2(av[2], a0.z); PACK2(av[3], a0.w);
#pragma unroll
            for (int i = 0; i < 4; ++i)
#pragma unroll
                for (int m = 0; m < 4; ++m)
                    FFMA2(acc[i][m], av[i], bb[m]);
        }

        if (more) {
#pragma unroll
            for (int s = 4; s < 8; ++s) {
                int idx = tid + s * NT;
                int r = idx & (BN - 1), k4 = idx >> 7;
                Bnxt[(k4 * 4 + 0) * BN + r] = st[s - 4].x;
                Bnxt[(k4 * 4 + 1) * BN + r] = st[s - 4].y;
                Bnxt[(k4 * 4 + 2) * BN + r] = st[s - 4].z;
                Bnxt[(k4 * 4 + 3) * BN + r] = st[s - 4].w;
            }
            if (tid < BN) {
                sxj[nxt * BN + tid] = g_sx2[jb + tid];
                scl[nxt * BN + tid] = g_scls[jb + tid];
            }
        }

        // ---- epilogue: monotone columns -> running class sums ----
#pragma unroll
        for (int m = 0; m < 4; ++m) {
#pragma unroll
            for (int p = 0; p < 2; ++p) {
                const int col = tx * 2 + 32 * m + p;
                const float xj = sxj[cur * BN + col];
                const int  cls = scl[cur * BN + col];
                if (cls != prevc) {
#pragma unroll
                    for (int i = 0; i < 4; ++i) {
                        atomicAdd(&sS[(ty * 4 + i) * NC + prevc], accr[i]);
                        accr[i] = 0.f;
                    }
                    prevc = cls;
                }
#pragma unroll
                for (int i = 0; i < 4; ++i) {
                    unsigned long long v = acc[i][m];
                    float dot = __uint_as_float(
                        p ? (unsigned)(v >> 32) : (unsigned)(v & 0xffffffffu));
                    float d = fmaxf(fmaf(-2.0f, dot, ax[i] + xj), 0.0f);
                    accr[i] += d;
                    mpv[i] = fmaxf(mpv[i], (cls == myl[i]) ? d : 0.0f);
                }
            }
        }
        if ((t & 7) == 7) {
#pragma unroll
            for (int i = 0; i < 4; ++i) {
                atomicAdd(&sS[(ty * 4 + i) * NC + prevc], accr[i]);
                accr[i] = 0.f;
            }
        }
    }

    // residual flush
#pragma unroll
    for (int i = 0; i < 4; ++i)
        atomicAdd(&sS[(ty * 4 + i) * NC + prevc], accr[i]);

    // mp reduce across tx (width-16 shfl), publish
#pragma unroll
    for (int off = 8; off >= 1; off >>= 1)
#pragma unroll
        for (int i = 0; i < 4; ++i)
            mpv[i] = fmaxf(mpv[i], __shfl_down_sync(0xffffffffu, mpv[i], off, 16));
    if (tx == 0) {
#pragma unroll
        for (int i = 0; i < 4; ++i)
            atomicMax(&g_mp[row0 + ty * 4 + i], __float_as_uint(mpv[i]));
    }

    __syncthreads();
    for (int p = tid; p < BM * NC; p += NT)
        atomicAdd(&g_S[row0 + p / NC][p % NC], sS[p]);
}

// ---------------------------------------------------------------------------
// Kernel 4: finalize — argmin, sorted-order pick, exact d_neg, loss
// ---------------------------------------------------------------------------
__global__ void bh_final(const float* __restrict__ E, const int* __restrict__ labels,
                         float* __restrict__ out)
{
    const int i = blockIdx.x * blockDim.x + threadIdx.x;

    float T = 0.f, S[NC];
#pragma unroll
    for (int c = 0; c < NC; c++) { S[c] = g_S[i][c]; T += S[c]; }

    float best = 3.4e38f;
    int   ks   = 0;
#pragma unroll
    for (int c = 0; c < NC; c++) {
        float nd = T - S[c];
        if (nd < best) { best = nd; ks = c; }
    }

    const int la = labels[i];
    int rem = ks, js = 0;
#pragma unroll
    for (int c = 0; c < NC; c++) {
        if (c == la) continue;
        int cn = g_count[c];
        if (rem < cn) { js = g_order[g_cstart[c] + rem]; rem = 0x7fffffff; }
        else rem -= cn;
    }

    const float4* pa = reinterpret_cast<const float4*>(E + (size_t)i * DD);
    const float4* pb = reinterpret_cast<const float4*>(E + (size_t)js * DD);
    float dot = 0.f;
#pragma unroll
    for (int k = 0; k < DD / 4; k++) {
        float4 a = pa[k], b = pb[k];
        dot += a.x * b.x + a.y * b.y + a.z * b.z + a.w * b.w;
    }
    float dn   = fmaxf(g_x2[i] + g_x2[js] - 2.0f * dot, 0.0f);
    float loss = fmaxf(__uint_as_float(g_mp[i]) - dn + 1.0f, 0.0f);

#pragma unroll
    for (int off = 16; off >= 1; off >>= 1)
        loss += __shfl_down_sync(0xffffffffu, loss, off);
    __shared__ float wsum[8];
    if ((threadIdx.x & 31) == 0) wsum[threadIdx.x >> 5] = loss;
    __syncthreads();
    if (threadIdx.x == 0) {
        float s = 0.f;
#pragma unroll
        for (int w = 0; w < 8; w++) s += wsum[w];
        atomicAdd(out, s * (1.0f / NN));
    }
}

// ---------------------------------------------------------------------------
extern "C" void kernel_launch(void* const* d_in, const int* in_sizes, int n_in,
                              void* d_out, int out_size)
{
    const float* E      = (const float*)d_in[0];
    const int*   labels = (const int*)d_in[1];
    float*       out    = (float*)d_out;

    const int smem = (DD * BM + 2 * DD * BN + 2 * BN + BM * NC) * 4 + 2 * BN * 4;
    cudaFuncSetAttribute(bh_main, cudaFuncAttributeMaxDynamicSharedMemorySize, smem);

    bh_prep<<<NN / 256, 256>>>(E, out);
    bh_table<<<1, 256>>>(labels);
    bh_main<<<dim3(NN / BM, JSPLIT), NT, smem>>>(E, labels);
    bh_final<<<NN / 256, 256>>>(E, labels, out);
}

// round 6
// speedup vs baseline: 1.8914x; 1.8914x over previous
#include <cuda_runtime.h>
#include <cstdint>

#define NN 8192
#define DD 128
#define NC 10
#define BT 128                 // tile edge
#define NB (NN / BT)           // 64 blocks per axis
#define NTILES (NB * (NB + 1) / 2)   // 2080

// ---- device globals ----
__device__ float    g_x2[NN];
__device__ float    g_S[NN][NC];      // indexed by SORTED position
__device__ unsigned g_mp[NN];         // indexed by SORTED position
__device__ int      g_order[NN];
__device__ int      g_scls[NN];
__device__ float    g_sx2[NN];
__device__ int      g_cstart[NC];
__device__ int      g_count[NC];

#define FFMA2(acc, a, b) \
    asm("fma.rn.f32x2 %0, %1, %2, %0;" : "+l"(acc) : "l"(a), "l"(b))
#define PACK2(dst, f) \
    asm("mov.b64 %0, {%1, %1};" : "=l"(dst) : "r"(__float_as_uint(f)))

// ---------------------------------------------------------------------------
// Kernel 1: row norms + zero g_S, g_mp, out
// ---------------------------------------------------------------------------
__global__ void bh_prep(const float* __restrict__ E, float* __restrict__ out)
{
    int r = blockIdx.x * blockDim.x + threadIdx.x;
    if (r == 0) out[0] = 0.0f;
    if (r < NN) {
        const float4* p = reinterpret_cast<const float4*>(E + (size_t)r * DD);
        float s = 0.f;
#pragma unroll
        for (int k = 0; k < DD / 4; k++) {
            float4 v = p[k];
            s += v.x * v.x + v.y * v.y + v.z * v.z + v.w * v.w;
        }
        g_x2[r] = s;
        g_mp[r] = 0u;
#pragma unroll
        for (int c = 0; c < NC; c++) g_S[r][c] = 0.f;
    }
}

// ---------------------------------------------------------------------------
// Kernel 2: counts, class starts, stable (class,index) sort -> order/cls/x2
// ---------------------------------------------------------------------------
__global__ void bh_table(const int* __restrict__ labels)
{
    __shared__ int sl[NN];
    __shared__ int cnt[NC][256];
    __shared__ int tot[NC], cst[NC];

    const int tid = threadIdx.x;
    for (int i = tid; i < NN; i += 256) sl[i] = labels[i];
    __syncthreads();

    const int base = tid * 32;
    int lc[NC];
#pragma unroll
    for (int c = 0; c < NC; c++) lc[c] = 0;
    for (int i = 0; i < 32; i++) {
        int lbl = sl[base + i];
#pragma unroll
        for (int c = 0; c < NC; c++) lc[c] += (lbl == c);
    }
#pragma unroll
    for (int c = 0; c < NC; c++) cnt[c][tid] = lc[c];
    __syncthreads();

    if (tid < NC) {
        int run = 0;
        for (int t = 0; t < 256; t++) { int tmp = cnt[tid][t]; cnt[tid][t] = run; run += tmp; }
        tot[tid] = run;
        g_count[tid] = run;
    }
    __syncthreads();
    if (tid == 0) {
        int run = 0;
        for (int c = 0; c < NC; c++) { cst[c] = run; g_cstart[c] = run; run += tot[c]; }
    }
    __syncthreads();

#pragma unroll
    for (int c = 0; c < NC; c++) lc[c] = 0;
    for (int i = 0; i < 32; i++) {
        int gi = base + i;
        int c  = sl[gi];
        int pos = cst[c] + cnt[c][tid] + lc[c]++;
        g_order[pos] = gi;
        g_scls[pos]  = c;
        g_sx2[pos]   = g_x2[gi];
    }
}

// ---------------------------------------------------------------------------
// Kernel 3: symmetric-tile Gram. One 128x128 tile per CTA over the upper
// triangle of blocks; each off-diagonal tile feeds BOTH row-side and
// col-side stats. Sorted order => each 128-block spans <= 2 classes.
// ---------------------------------------------------------------------------
__global__ __launch_bounds__(256, 1)
void bh_main(const float* __restrict__ E)
{
    extern __shared__ float sm[];
    float* As  = sm;                    // [DD][BT]
    float* Bsm = As + DD * BT;          // [DD][BT]
    float* sCA = Bsm + DD * BT;         // [16][128] col-side sums, row-class A
    float* sCB = sCA + 16 * 128;        // [16][128] col-side sums, row-class B
    float* sMp = sCB + 16 * 128;        // [16][128] col-side same-class max
    float* sxj = sMp + 16 * 128;        // [128]
    __shared__ int sb_col, sb_row;

    const int tid = threadIdx.x;
    const int tx  = tid & 15;
    const int ty  = tid >> 4;

    // triangular decode
    int b = blockIdx.x, bi = 0;
    while (b >= NB - bi) { b -= NB - bi; ++bi; }
    const int bj = bi + b;
    const bool diag = (bi == bj);
    const int rowbase = bi * BT;
    const int jbase   = bj * BT;

    if (tid == 0) { sb_col = BT; sb_row = BT; }
    __syncthreads();
    if (tid < BT - 1) {
        if (g_scls[jbase + tid + 1]   != g_scls[jbase + tid])   atomicMin(&sb_col, tid + 1);
        if (g_scls[rowbase + tid + 1] != g_scls[rowbase + tid]) atomicMin(&sb_row, tid + 1);
    }

    // ---- load A (and B if off-diagonal), k-major, gathered by sorted order
#pragma unroll
    for (int it = 0; it < 16; ++it) {
        int idx = tid + it * 256;
        int r   = idx & (BT - 1);
        int k4  = idx >> 7;
        float4 v = *reinterpret_cast<const float4*>(
            E + (size_t)g_order[rowbase + r] * DD + k4 * 4);
        As[(k4 * 4 + 0) * BT + r] = v.x;
        As[(k4 * 4 + 1) * BT + r] = v.y;
        As[(k4 * 4 + 2) * BT + r] = v.z;
        As[(k4 * 4 + 3) * BT + r] = v.w;
    }
    if (!diag) {
#pragma unroll
        for (int it = 0; it < 16; ++it) {
            int idx = tid + it * 256;
            int r   = idx & (BT - 1);
            int k4  = idx >> 7;
            float4 v = *reinterpret_cast<const float4*>(
                E + (size_t)g_order[jbase + r] * DD + k4 * 4);
            Bsm[(k4 * 4 + 0) * BT + r] = v.x;
            Bsm[(k4 * 4 + 1) * BT + r] = v.y;
            Bsm[(k4 * 4 + 2) * BT + r] = v.z;
            Bsm[(k4 * 4 + 3) * BT + r] = v.w;
        }
    }
    if (tid < BT) sxj[tid] = g_sx2[jbase + tid];
    __syncthreads();

    const float* Bs = diag ? As : Bsm;
    const int scol = sb_col, srow = sb_row;
    const int cAc = g_scls[jbase],   cBc = g_scls[jbase + BT - 1];
    const int cAr = g_scls[rowbase], cBr = g_scls[rowbase + BT - 1];

    // ---- 128x128x128 gram, 8x8 micro-tile, j-packed f32x2 ----
    unsigned long long acc[8][4];
#pragma unroll
    for (int i = 0; i < 8; ++i)
#pragma unroll
        for (int m = 0; m < 4; ++m) acc[i][m] = 0ull;

#pragma unroll 4
    for (int k = 0; k < DD; ++k) {
        float4 a0 = *reinterpret_cast<const float4*>(&As[k * BT + ty * 8]);
        float4 a1 = *reinterpret_cast<const float4*>(&As[k * BT + ty * 8 + 4]);
        unsigned long long bb[4];
#pragma unroll
        for (int m = 0; m < 4; ++m)
            bb[m] = *reinterpret_cast<const unsigned long long*>(
                &Bs[k * BT + tx * 2 + 32 * m]);
        unsigned long long av[8];
        PACK2(av[0], a0.x); PACK2(av[1], a0.y); PACK2(av[2], a0.z); PACK2(av[3], a0.w);
        PACK2(av[4], a1.x); PACK2(av[5], a1.y); PACK2(av[6], a1.z); PACK2(av[7], a1.w);
#pragma unroll
        for (int i = 0; i < 8; ++i)
#pragma unroll
            for (int m = 0; m < 4; ++m)
                FFMA2(acc[i][m], av[i], bb[m]);
    }

    // ---- epilogue ----
    float ax[8];
    int   rcls[8];
#pragma unroll
    for (int i = 0; i < 8; ++i) {
        ax[i]   = g_sx2[rowbase + ty * 8 + i];
        rcls[i] = (ty * 8 + i < srow) ? cAr : cBr;
    }
    float accA[8], accB[8], mpv[8];
#pragma unroll
    for (int i = 0; i < 8; ++i) { accA[i] = 0.f; accB[i] = 0.f; mpv[i] = 0.f; }

#pragma unroll
    for (int m = 0; m < 4; ++m) {
#pragma unroll
        for (int p = 0; p < 2; ++p) {
            const int  col  = tx * 2 + 32 * m + p;
            const bool isA  = col < scol;
            const int  ccol = isA ? cAc : cBc;
            const float xj  = sxj[col];
            float sA = 0.f, sB = 0.f, mpc = 0.f;
#pragma unroll
            for (int i = 0; i < 8; ++i) {
                unsigned long long v = acc[i][m];
                float dot = __uint_as_float(
                    p ? (unsigned)(v >> 32) : (unsigned)(v & 0xffffffffu));
                float d = fmaxf(fmaf(-2.0f, dot, ax[i] + xj), 0.0f);
                if (isA) accA[i] += d; else accB[i] += d;          // row-side sums
                if (rcls[i] == ccol) mpv[i] = fmaxf(mpv[i], d);    // row-side max
                if (ty * 8 + i < srow) sA += d; else sB += d;      // col-side sums
                if (rcls[i] == ccol) mpc = fmaxf(mpc, d);          // col-side max
            }
            if (!diag) {
                sCA[ty * 128 + col] = sA;
                sCB[ty * 128 + col] = sB;
                sMp[ty * 128 + col] = mpc;
            }
        }
    }

    // row-side reduce across tx (width-16 shfl) and publish
#pragma unroll
    for (int off = 8; off >= 1; off >>= 1) {
#pragma unroll
        for (int i = 0; i < 8; ++i) {
            accA[i] += __shfl_down_sync(0xffffffffu, accA[i], off, 16);
            accB[i] += __shfl_down_sync(0xffffffffu, accB[i], off, 16);
            mpv[i]   = fmaxf(mpv[i], __shfl_down_sync(0xffffffffu, mpv[i], off, 16));
        }
    }
    if (tx == 0) {
#pragma unroll
        for (int i = 0; i < 8; ++i) {
            const int rp = rowbase + ty * 8 + i;
            atomicAdd(&g_S[rp][cAc], accA[i]);
            if (scol < BT) atomicAdd(&g_S[rp][cBc], accB[i]);
            atomicMax(&g_mp[rp], __float_as_uint(mpv[i]));
        }
    }

    // col-side reduce and publish (off-diagonal only)
    if (!diag) {
        __syncthreads();
        if (tid < BT) {
            const int col = tid;
            float sA = 0.f, sB = 0.f;
#pragma unroll
            for (int t2 = 0; t2 < 16; ++t2) {
                sA += sCA[t2 * 128 + col];
                sB += sCB[t2 * 128 + col];
            }
            const int cp = jbase + col;
            atomicAdd(&g_S[cp][cAr], sA);
            if (srow < BT) atomicAdd(&g_S[cp][cBr], sB);
        } else {
            const int col = tid - BT;
            float mpc = 0.f;
#pragma unroll
            for (int t2 = 0; t2 < 16; ++t2)
                mpc = fmaxf(mpc, sMp[t2 * 128 + col]);
            atomicMax(&g_mp[jbase + col], __float_as_uint(mpc));
        }
    }
}

// ---------------------------------------------------------------------------
// Kernel 4: finalize — per sorted position: argmin, class walk, exact d_neg
// ---------------------------------------------------------------------------
__global__ void bh_final(const float* __restrict__ E, float* __restrict__ out)
{
    const int p = blockIdx.x * blockDim.x + threadIdx.x;

    float T = 0.f, S[NC];
#pragma unroll
    for (int c = 0; c < NC; c++) { S[c] = g_S[p][c]; T += S[c]; }

    float best = 3.4e38f;
    int   ks   = 0;
#pragma unroll
    for (int c = 0; c < NC; c++) {
        float nd = T - S[c];
        if (nd < best) { best = nd; ks = c; }
    }

    const int la = g_scls[p];
    int rem = ks, js = 0;
#pragma unroll
    for (int c = 0; c < NC; c++) {
        if (c == la) continue;
        int cn = g_count[c];
        if (rem < cn) { js = g_order[g_cstart[c] + rem]; rem = 0x7fffffff; }
        else rem -= cn;
    }

    const int gi = g_order[p];
    const float4* pa = reinterpret_cast<const float4*>(E + (size_t)gi * DD);
    const float4* pb = reinterpret_cast<const float4*>(E + (size_t)js * DD);
    float dot = 0.f;
#pragma unroll
    for (int k = 0; k < DD / 4; k++) {
        float4 a = pa[k], bv = pb[k];
        dot += a.x * bv.x + a.y * bv.y + a.z * bv.z + a.w * bv.w;
    }
    float dn   = fmaxf(g_x2[gi] + g_x2[js] - 2.0f * dot, 0.0f);
    float loss = fmaxf(__uint_as_float(g_mp[p]) - dn + 1.0f, 0.0f);

#pragma unroll
    for (int off = 16; off >= 1; off >>= 1)
        loss += __shfl_down_sync(0xffffffffu, loss, off);
    __shared__ float wsum[8];
    if ((threadIdx.x & 31) == 0) wsum[threadIdx.x >> 5] = loss;
    __syncthreads();
    if (threadIdx.x == 0) {
        float s = 0.f;
#pragma unroll
        for (int w = 0; w < 8; w++) s += wsum[w];
        atomicAdd(out, s * (1.0f / NN));
    }
}

// ---------------------------------------------------------------------------
extern "C" void kernel_launch(void* const* d_in, const int* in_sizes, int n_in,
                              void* d_out, int out_size)
{
    const float* E      = (const float*)d_in[0];
    const int*   labels = (const int*)d_in[1];
    float*       out    = (float*)d_out;

    const int smem = (2 * DD * BT + 3 * 16 * 128 + 128) * 4;
    cudaFuncSetAttribute(bh_main, cudaFuncAttributeMaxDynamicSharedMemorySize, smem);

    bh_prep<<<NN / 256, 256>>>(E, out);
    bh_table<<<1, 256>>>(labels);
    bh_main<<<NTILES, 256, smem>>>(E);
    bh_final<<<NN / 256, 256>>>(E, out);
}